// round 6
// baseline (speedup 1.0000x reference)
#include <cuda_runtime.h>

// Problem constants
#define HH 192
#define WW 192
#define HW (192*192)
#define BB 4
#define DD 8
#define NF 32
#define NFH 40
#define CGATE 56
#define EPS 1e-5f

// ---------------- scratch (device globals; no allocation) ----------------
__device__ float g_hs[BB*8*HW];
__device__ float g_cs[BB*8*HW];
__device__ float g_fic[BB*24*HW];      // raw f,i,c gate conv outputs
__device__ float g_r[BB*NFH*HW];       // [cs(8), sigmoid(q)(32)]
__device__ float g_y0[BB*NFH*HW];      // conv0 raw output (pre-BN)
__device__ float g_y1[BB*NFH*HW];      // conv1 raw output (pre-BN)
__device__ float g_wgate[CGATE*NFH*9];
__device__ float g_bgate[CGATE];
__device__ float g_wtail[11*NFH*25];
__device__ float g_btail[11];
__device__ float g_partS[NFH*288];
__device__ float g_partQ[NFH*288];
__device__ float g_bna[2][NFH];        // BN fused scale
__device__ float g_bnb[2][NFH];        // BN fused shift

// ---------------- helpers ----------------
__device__ __forceinline__ float sigm(float x) { return 1.f / (1.f + expf(-x)); }

// ---------------- init / prep ----------------
__global__ void zero_state() {
    int i = blockIdx.x * blockDim.x + threadIdx.x;
    if (i < BB*8*HW) { g_hs[i] = 0.f; g_cs[i] = 0.f; }
}

__global__ void prep_gate(const float* __restrict__ Wf, const float* __restrict__ bf,
                          const float* __restrict__ Wi, const float* __restrict__ bi,
                          const float* __restrict__ Wc, const float* __restrict__ bc,
                          const float* __restrict__ Wq, const float* __restrict__ bq) {
    int i = blockIdx.x * blockDim.x + threadIdx.x;
    const int WSZ = NFH * 9;
    if (i < CGATE * WSZ) {
        int o = i / WSZ, r = i % WSZ;
        float v;
        if (o < 8)       v = Wf[o * WSZ + r];
        else if (o < 16) v = Wi[(o - 8) * WSZ + r];
        else if (o < 24) v = Wc[(o - 16) * WSZ + r];
        else             v = Wq[(o - 24) * WSZ + r];
        g_wgate[i] = v;
    }
    if (i < CGATE) {
        float bv = (i < 8) ? bf[i] : (i < 16) ? bi[i - 8] : (i < 24) ? bc[i - 16] : bq[i - 24];
        g_bgate[i] = bv;
    }
}

__global__ void prep_tail(const float* __restrict__ W2, const float* __restrict__ b2w,
                          const float* __restrict__ Wh, const float* __restrict__ bh) {
    int i = blockIdx.x * blockDim.x + threadIdx.x;
    if (i < 11 * NFH * 25) {
        int o = i / (NFH * 25), r = i % (NFH * 25);
        int ci = r / 25, k = r % 25, ky = k / 5, kx = k % 5;
        float v;
        if (o < 3) {
            v = W2[(o * NFH + ci) * 25 + k];
        } else {
            int oo = o - 3;
            v = (ky >= 1 && ky <= 3 && kx >= 1 && kx <= 3)
                    ? Wh[(oo * NFH + ci) * 9 + (ky - 1) * 3 + (kx - 1)]
                    : 0.f;
        }
        g_wtail[i] = v;
    }
    if (i < 11) g_btail[i] = (i < 3) ? b2w[i] : bh[i - 3];
}

// ---------------- gate conv (3x3, 40 -> 56, 8 out-ch per block) ----------------
// blockDim (8,16): tile 32x16 px, 4 px/thread, 8 out channels/thread.
__global__ __launch_bounds__(128) void gates_kernel(const float* __restrict__ xin, int t) {
    __shared__ float swT[NFH * 9 * 8];   // [ci][k][co] transposed, 2880 floats
    __shared__ float st[18][36];
    int n = blockIdx.z / 7, grp = blockIdx.z % 7;
    int tx = threadIdx.x, ty = threadIdx.y;
    int tid = ty * 8 + tx;
    // load + transpose weight slice
    for (int i = tid; i < 8 * NFH * 9; i += 128) {
        int o = i / (NFH * 9), r = i % (NFH * 9);
        swT[r * 8 + o] = g_wgate[(grp * 8) * (NFH * 9) + i];
    }
    float acc[8][4];
    #pragma unroll
    for (int c = 0; c < 8; c++) { acc[c][0]=acc[c][1]=acc[c][2]=acc[c][3]=0.f; }
    int y0 = blockIdx.y * 16, x0 = blockIdx.x * 32;

    for (int ci = 0; ci < NFH; ci++) {
        const float* src = (ci < NF)
            ? (xin + ((size_t)(n * DD + t) * NF + ci) * HW)
            : (g_hs + ((size_t)n * 8 + (ci - NF)) * HW);
        __syncthreads();
        for (int i = tid; i < 18 * 34; i += 128) {
            int r = i / 34, c = i % 34;
            int yy = y0 - 1 + r, xx = x0 - 1 + c;
            st[r][c] = (yy >= 0 && yy < HH && xx >= 0 && xx < WW) ? src[yy * WW + xx] : 0.f;
        }
        __syncthreads();
        #pragma unroll
        for (int ky = 0; ky < 3; ky++) {
            float iv[6];
            float4 t0 = *(const float4*)&st[ty + ky][tx * 4];
            iv[0]=t0.x; iv[1]=t0.y; iv[2]=t0.z; iv[3]=t0.w;
            iv[4] = st[ty + ky][tx * 4 + 4];
            iv[5] = st[ty + ky][tx * 4 + 5];
            #pragma unroll
            for (int kx = 0; kx < 3; kx++) {
                const float* wv = &swT[(ci * 9 + ky * 3 + kx) * 8];
                float4 wA = *(const float4*)wv;
                float4 wB = *(const float4*)(wv + 4);
                #pragma unroll
                for (int p = 0; p < 4; p++) {
                    float x = iv[p + kx];
                    acc[0][p] = fmaf(x, wA.x, acc[0][p]);
                    acc[1][p] = fmaf(x, wA.y, acc[1][p]);
                    acc[2][p] = fmaf(x, wA.z, acc[2][p]);
                    acc[3][p] = fmaf(x, wA.w, acc[3][p]);
                    acc[4][p] = fmaf(x, wB.x, acc[4][p]);
                    acc[5][p] = fmaf(x, wB.y, acc[5][p]);
                    acc[6][p] = fmaf(x, wB.z, acc[6][p]);
                    acc[7][p] = fmaf(x, wB.w, acc[7][p]);
                }
            }
        }
    }
    int yy = y0 + ty, xb = x0 + tx * 4;
    #pragma unroll
    for (int co = 0; co < 8; co++) {
        int oc = grp * 8 + co;
        float b = g_bgate[oc];
        float4 v;
        v.x = acc[co][0] + b; v.y = acc[co][1] + b; v.z = acc[co][2] + b; v.w = acc[co][3] + b;
        if (oc < 24) {
            *(float4*)&g_fic[((size_t)n * 24 + oc) * HW + yy * WW + xb] = v;
        } else {
            v.x = sigm(v.x); v.y = sigm(v.y); v.z = sigm(v.z); v.w = sigm(v.w);
            *(float4*)&g_r[((size_t)n * NFH + 8 + (oc - 24)) * HW + yy * WW + xb] = v;
        }
    }
}

// ---------------- LSTM cell state update ----------------
__global__ void cs_update() {
    int i = blockIdx.x * 256 + threadIdx.x;
    if (i >= BB * 8 * HW) return;
    int n = i / (8 * HW);
    int r = i % (8 * HW);
    int c = r / HW, p = r % HW;
    size_t base = (size_t)n * 24 * HW + p;
    float zf = g_fic[base + (size_t)c * HW];
    float zi = g_fic[base + (size_t)(8 + c) * HW];
    float zc = g_fic[base + (size_t)(16 + c) * HW];
    float cs = sigm(zf) * g_cs[i] + sigm(zi) * tanhf(zc);
    g_cs[i] = cs;
    g_r[((size_t)n * NFH + c) * HW + p] = cs;
}

// ---------------- 5x5 conv 40->40 with BN-partial emission ----------------
// PHASE 0: in = g_r (raw), out = g_y0.  PHASE 1: in = BN0+relu(g_y0), out = g_y1.
template <int PHASE>
__global__ __launch_bounds__(128) void conv5_kernel(const float* __restrict__ Wt) {
    __shared__ float swT[NFH * 25 * 8];   // [ci][k][co], 8000 floats
    __shared__ float st[20][36];
    __shared__ float red[2][4][8];
    int n = blockIdx.z / 5, cog = blockIdx.z % 5;
    int tx = threadIdx.x, ty = threadIdx.y;
    int tid = ty * 8 + tx;
    for (int i = tid; i < 8 * NFH * 25; i += 128) {
        int o = i / (NFH * 25), r = i % (NFH * 25);
        swT[r * 8 + o] = Wt[(cog * 8) * (NFH * 25) + i];
    }
    float acc[8][4];
    #pragma unroll
    for (int c = 0; c < 8; c++) { acc[c][0]=acc[c][1]=acc[c][2]=acc[c][3]=0.f; }
    int y0 = blockIdx.y * 16, x0 = blockIdx.x * 32;

    for (int ci = 0; ci < NFH; ci++) {
        const float* src = (PHASE ? g_y0 : g_r) + ((size_t)n * NFH + ci) * HW;
        float a = 0.f, b = 0.f;
        if (PHASE) { a = g_bna[0][ci]; b = g_bnb[0][ci]; }
        __syncthreads();
        for (int i = tid; i < 20 * 36; i += 128) {
            int r = i / 36, c = i % 36;
            int yy = y0 - 2 + r, xx = x0 - 2 + c;
            float v = 0.f;
            if (yy >= 0 && yy < HH && xx >= 0 && xx < WW) {
                v = src[yy * WW + xx];
                if (PHASE) v = fmaxf(0.f, fmaf(v, a, b));
            }
            st[r][c] = v;
        }
        __syncthreads();
        #pragma unroll
        for (int ky = 0; ky < 5; ky++) {
            float iv[8];
            float4 t0 = *(const float4*)&st[ty + ky][tx * 4];
            float4 t1 = *(const float4*)&st[ty + ky][tx * 4 + 4];
            iv[0]=t0.x; iv[1]=t0.y; iv[2]=t0.z; iv[3]=t0.w;
            iv[4]=t1.x; iv[5]=t1.y; iv[6]=t1.z; iv[7]=t1.w;
            #pragma unroll
            for (int kx = 0; kx < 5; kx++) {
                const float* wv = &swT[(ci * 25 + ky * 5 + kx) * 8];
                float4 wA = *(const float4*)wv;
                float4 wB = *(const float4*)(wv + 4);
                #pragma unroll
                for (int p = 0; p < 4; p++) {
                    float x = iv[p + kx];
                    acc[0][p] = fmaf(x, wA.x, acc[0][p]);
                    acc[1][p] = fmaf(x, wA.y, acc[1][p]);
                    acc[2][p] = fmaf(x, wA.z, acc[2][p]);
                    acc[3][p] = fmaf(x, wA.w, acc[3][p]);
                    acc[4][p] = fmaf(x, wB.x, acc[4][p]);
                    acc[5][p] = fmaf(x, wB.y, acc[5][p]);
                    acc[6][p] = fmaf(x, wB.z, acc[6][p]);
                    acc[7][p] = fmaf(x, wB.w, acc[7][p]);
                }
            }
        }
    }
    // write raw conv out + BN partials
    float* outp = PHASE ? g_y1 : g_y0;
    int yy = y0 + ty, xb = x0 + tx * 4;
    float s[8], q[8];
    #pragma unroll
    for (int co = 0; co < 8; co++) {
        float4 v; v.x = acc[co][0]; v.y = acc[co][1]; v.z = acc[co][2]; v.w = acc[co][3];
        *(float4*)&outp[((size_t)n * NFH + cog * 8 + co) * HW + yy * WW + xb] = v;
        s[co] = v.x + v.y + v.z + v.w;
        q[co] = v.x * v.x + v.y * v.y + v.z * v.z + v.w * v.w;
    }
    int lane = tid & 31, warp = tid >> 5;
    #pragma unroll
    for (int off = 16; off; off >>= 1) {
        #pragma unroll
        for (int co = 0; co < 8; co++) {
            s[co] += __shfl_down_sync(0xffffffffu, s[co], off);
            q[co] += __shfl_down_sync(0xffffffffu, q[co], off);
        }
    }
    if (lane == 0) {
        #pragma unroll
        for (int co = 0; co < 8; co++) { red[0][warp][co] = s[co]; red[1][warp][co] = q[co]; }
    }
    __syncthreads();
    if (tid < 8) {
        float S = red[0][0][tid] + red[0][1][tid] + red[0][2][tid] + red[0][3][tid];
        float Q = red[1][0][tid] + red[1][1][tid] + red[1][2][tid] + red[1][3][tid];
        int ch = cog * 8 + tid;
        int bxy = (n * 12 + blockIdx.y) * 6 + blockIdx.x;
        g_partS[ch * 288 + bxy] = S;
        g_partQ[ch * 288 + bxy] = Q;
    }
}

// ---------------- BN statistics finalize ----------------
__global__ void bn_reduce(int phase, const float* __restrict__ gamma, const float* __restrict__ beta) {
    int ch = blockIdx.x;
    int tid = threadIdx.x;
    __shared__ float ss[128], sq[128];
    float s = 0.f, q = 0.f;
    for (int i = tid; i < 288; i += 128) { s += g_partS[ch * 288 + i]; q += g_partQ[ch * 288 + i]; }
    ss[tid] = s; sq[tid] = q;
    __syncthreads();
    for (int off = 64; off; off >>= 1) {
        if (tid < off) { ss[tid] += ss[tid + off]; sq[tid] += sq[tid + off]; }
        __syncthreads();
    }
    if (tid == 0) {
        const float N = (float)(BB * HW);
        float mean = ss[0] / N;
        float var = sq[0] / N - mean * mean;
        float inv = rsqrtf(var + EPS);
        float a = gamma[ch] * inv;
        g_bna[phase][ch] = a;
        g_bnb[phase][ch] = beta[ch] - mean * a;
    }
}

// ---------------- tail: combined 5x5 conv, 40 -> 11 (3 depth + 8 h) ----------------
__global__ __launch_bounds__(128) void tail_kernel(float* __restrict__ outp, int t) {
    __shared__ float sw[11 * NFH * 25];   // [co][ci][25], 11000 floats
    __shared__ float st[20][36];
    int n = blockIdx.z;
    int tx = threadIdx.x, ty = threadIdx.y;
    int tid = ty * 8 + tx;
    for (int i = tid; i < 11 * NFH * 25; i += 128) sw[i] = g_wtail[i];
    float acc[11][4];
    #pragma unroll
    for (int c = 0; c < 11; c++) { acc[c][0]=acc[c][1]=acc[c][2]=acc[c][3]=0.f; }
    int y0 = blockIdx.y * 16, x0 = blockIdx.x * 32;

    for (int ci = 0; ci < NFH; ci++) {
        const float* src = g_y1 + ((size_t)n * NFH + ci) * HW;
        float a = g_bna[1][ci], b = g_bnb[1][ci];
        __syncthreads();
        for (int i = tid; i < 20 * 36; i += 128) {
            int r = i / 36, c = i % 36;
            int yy = y0 - 2 + r, xx = x0 - 2 + c;
            float v = 0.f;
            if (yy >= 0 && yy < HH && xx >= 0 && xx < WW)
                v = fmaxf(0.f, fmaf(src[yy * WW + xx], a, b));
            st[r][c] = v;
        }
        __syncthreads();
        #pragma unroll
        for (int ky = 0; ky < 5; ky++) {
            float iv[8];
            float4 t0 = *(const float4*)&st[ty + ky][tx * 4];
            float4 t1 = *(const float4*)&st[ty + ky][tx * 4 + 4];
            iv[0]=t0.x; iv[1]=t0.y; iv[2]=t0.z; iv[3]=t0.w;
            iv[4]=t1.x; iv[5]=t1.y; iv[6]=t1.z; iv[7]=t1.w;
            #pragma unroll
            for (int co = 0; co < 11; co++) {
                const float* wp = &sw[(co * NFH + ci) * 25 + ky * 5];
                float w0 = wp[0], w1 = wp[1], w2 = wp[2], w3 = wp[3], w4 = wp[4];
                #pragma unroll
                for (int p = 0; p < 4; p++) {
                    float v = fmaf(iv[p], w0, fmaf(iv[p+1], w1, fmaf(iv[p+2], w2,
                              fmaf(iv[p+3], w3, iv[p+4] * w4))));
                    acc[co][p] += v;
                }
            }
        }
    }
    int yy = y0 + ty, xb = x0 + tx * 4;
    #pragma unroll
    for (int co = 0; co < 11; co++) {
        float b = g_btail[co];
        float4 v; v.x = acc[co][0]+b; v.y = acc[co][1]+b; v.z = acc[co][2]+b; v.w = acc[co][3]+b;
        if (co < 3) {
            *(float4*)&outp[(((size_t)n * 3 + co) * DD + t) * HW + yy * WW + xb] = v;
        } else {
            *(float4*)&g_hs[((size_t)n * 8 + (co - 3)) * HW + yy * WW + xb] = v;
        }
    }
}

// ---------------- launcher ----------------
extern "C" void kernel_launch(void* const* d_in, const int* in_sizes, int n_in,
                              void* d_out, int out_size) {
    const float* x1  = (const float*)d_in[0];
    const float* x2  = (const float*)d_in[1];
    const float* Wf  = (const float*)d_in[2];
    const float* bf  = (const float*)d_in[3];
    const float* Wi  = (const float*)d_in[4];
    const float* bi  = (const float*)d_in[5];
    const float* Wc  = (const float*)d_in[6];
    const float* bc  = (const float*)d_in[7];
    const float* Wq  = (const float*)d_in[8];
    const float* bq  = (const float*)d_in[9];
    const float* W0  = (const float*)d_in[10];
    const float* g0  = (const float*)d_in[11];
    const float* be0 = (const float*)d_in[12];
    const float* W1  = (const float*)d_in[13];
    const float* g1  = (const float*)d_in[14];
    const float* be1 = (const float*)d_in[15];
    const float* W2  = (const float*)d_in[16];
    const float* b2w = (const float*)d_in[17];
    const float* Wh  = (const float*)d_in[18];
    const float* bh  = (const float*)d_in[19];
    float* out = (float*)d_out;

    dim3 cb(8, 16, 1);
    dim3 gGate(6, 12, BB * 7);
    dim3 gConv(6, 12, BB * 5);
    dim3 gTail(6, 12, BB);

    zero_state<<<(BB*8*HW + 255) / 256, 256>>>();
    prep_gate<<<(CGATE*NFH*9 + 255) / 256, 256>>>(Wf, bf, Wi, bi, Wc, bc, Wq, bq);
    prep_tail<<<(11*NFH*25 + 255) / 256, 256>>>(W2, b2w, Wh, bh);

    const size_t OUT_HALF = (size_t)BB * 3 * DD * HW;
    for (int t = 0; t < DD; t++) {
        for (int cell = 0; cell < 2; cell++) {
            gates_kernel<<<gGate, cb>>>(cell ? x2 : x1, t);
            cs_update<<<(BB*8*HW + 255) / 256, 256>>>();
            conv5_kernel<0><<<gConv, cb>>>(W0);
            bn_reduce<<<NFH, 128>>>(0, g0, be0);
            conv5_kernel<1><<<gConv, cb>>>(W1);
            bn_reduce<<<NFH, 128>>>(1, g1, be1);
            tail_kernel<<<gTail, cb>>>(out + (size_t)cell * OUT_HALF, t);
        }
    }
}

// round 7
// speedup vs baseline: 1.0479x; 1.0479x over previous
#include <cuda_runtime.h>

// Problem constants
#define HH 192
#define WW 192
#define HW (192*192)
#define BB 4
#define DD 8
#define NF 32
#define NFH 40
#define CGATE 56
#define EPS 1e-5f
#define NPART 144   // BB * 12 * 3 BN partial blocks

// ---------------- scratch (device globals; no allocation) ----------------
__device__ float g_hs[BB*8*HW];
__device__ float g_cs[BB*8*HW];
__device__ float g_fic[BB*24*HW];      // raw f,i,c gate conv outputs
__device__ float g_r[BB*NFH*HW];       // [cs(8), sigmoid(q)(32)]
__device__ float g_y0[BB*NFH*HW];      // conv0 raw output (pre-BN)
__device__ float g_y1[BB*NFH*HW];      // conv1 raw output (pre-BN)
__device__ float g_wgate[CGATE*NFH*9];
__device__ float g_bgate[CGATE];
__device__ float g_wtailT[NFH*25*12];  // [ci][tap][co(12, pad)] transposed tail weights
__device__ float g_btail[11];
__device__ float g_partS[NFH*NPART];
__device__ float g_partQ[NFH*NPART];
__device__ float g_bna[2][NFH];        // BN fused scale
__device__ float g_bnb[2][NFH];        // BN fused shift

// ---------------- helpers ----------------
__device__ __forceinline__ float sigm(float x) { return 1.f / (1.f + expf(-x)); }

// pack same fp32 into both lanes of a 64-bit f32x2
__device__ __forceinline__ unsigned long long pack2(float x) {
    unsigned long long r;
    asm("mov.b64 %0, {%1, %1};" : "=l"(r) : "r"(__float_as_uint(x)));
    return r;
}
// packed dual fp32 FMA: acc.lo += x.lo*w.lo ; acc.hi += x.hi*w.hi
__device__ __forceinline__ void fma2(unsigned long long& a, unsigned long long x, unsigned long long w) {
    asm("fma.rn.f32x2 %0, %1, %2, %0;" : "+l"(a) : "l"(x), "l"(w));
}
__device__ __forceinline__ float2 unpack2(unsigned long long v) {
    unsigned int lo, hi;
    asm("mov.b64 {%0, %1}, %2;" : "=r"(lo), "=r"(hi) : "l"(v));
    return make_float2(__uint_as_float(lo), __uint_as_float(hi));
}

// ---------------- init / prep ----------------
__global__ void zero_state() {
    int i = blockIdx.x * blockDim.x + threadIdx.x;
    if (i < BB*8*HW) { g_hs[i] = 0.f; g_cs[i] = 0.f; }
}

__global__ void prep_gate(const float* __restrict__ Wf, const float* __restrict__ bf,
                          const float* __restrict__ Wi, const float* __restrict__ bi,
                          const float* __restrict__ Wc, const float* __restrict__ bc,
                          const float* __restrict__ Wq, const float* __restrict__ bq) {
    int i = blockIdx.x * blockDim.x + threadIdx.x;
    const int WSZ = NFH * 9;
    if (i < CGATE * WSZ) {
        int o = i / WSZ, r = i % WSZ;
        float v;
        if (o < 8)       v = Wf[o * WSZ + r];
        else if (o < 16) v = Wi[(o - 8) * WSZ + r];
        else if (o < 24) v = Wc[(o - 16) * WSZ + r];
        else             v = Wq[(o - 24) * WSZ + r];
        g_wgate[i] = v;
    }
    if (i < CGATE) {
        float bv = (i < 8) ? bf[i] : (i < 16) ? bi[i - 8] : (i < 24) ? bc[i - 16] : bq[i - 24];
        g_bgate[i] = bv;
    }
}

// tail weights: [ci][tap][co], co padded 11->12 (co<3: W2 depth, co 3..10: Wh 3x3 embedded, co11: 0)
__global__ void prep_tail(const float* __restrict__ W2, const float* __restrict__ b2w,
                          const float* __restrict__ Wh, const float* __restrict__ bh) {
    int i = blockIdx.x * blockDim.x + threadIdx.x;
    if (i < NFH * 25 * 12) {
        int o = i % 12;
        int rt = i / 12;            // ci*25 + tap
        int ci = rt / 25, k = rt % 25, ky = k / 5, kx = k % 5;
        float v = 0.f;
        if (o < 3) {
            v = W2[(o * NFH + ci) * 25 + k];
        } else if (o < 11) {
            int oo = o - 3;
            if (ky >= 1 && ky <= 3 && kx >= 1 && kx <= 3)
                v = Wh[(oo * NFH + ci) * 9 + (ky - 1) * 3 + (kx - 1)];
        }
        g_wtailT[i] = v;
    }
    if (i < 11) g_btail[i] = (i < 3) ? b2w[i] : bh[i - 3];
}

// ---------------- gate conv (3x3, 40 -> 56), f32x2, 64x16 tile, 8px x 8co/thread --------
__global__ __launch_bounds__(128, 3) void gates_kernel(const float* __restrict__ xin, int t) {
    __shared__ float swT[NFH * 9 * 8];    // [ci][k][co] 2880 f
    __shared__ float st[2][18][72];       // ping-pong tile, 66 cols used
    int n = blockIdx.z / 7, grp = blockIdx.z % 7;
    int tx = threadIdx.x, ty = threadIdx.y;
    int tid = ty * 8 + tx;
    for (int i = tid; i < 8 * NFH * 9; i += 128) {
        int o = i / (NFH * 9), r = i % (NFH * 9);
        swT[r * 8 + o] = g_wgate[(grp * 8) * (NFH * 9) + i];
    }
    unsigned long long acc[8][4];
    #pragma unroll
    for (int p = 0; p < 8; p++) { acc[p][0]=acc[p][1]=acc[p][2]=acc[p][3]=0ull; }
    int y0 = blockIdx.y * 16, x0 = blockIdx.x * 64;

    auto loadci = [&](int ci, int buf) {
        const float* src = (ci < NF)
            ? (xin + ((size_t)(n * DD + t) * NF + ci) * HW)
            : (g_hs + ((size_t)n * 8 + (ci - NF)) * HW);
        for (int i = tid; i < 18 * 66; i += 128) {
            int r = i / 66, c = i % 66;
            int yy = y0 - 1 + r, xx = x0 - 1 + c;
            st[buf][r][c] = (yy >= 0 && yy < HH && xx >= 0 && xx < WW) ? src[yy * WW + xx] : 0.f;
        }
    };

    loadci(0, 0);
    __syncthreads();
    for (int ci = 0; ci < NFH; ci++) {
        if (ci + 1 < NFH) loadci(ci + 1, (ci + 1) & 1);
        int buf = ci & 1;
        #pragma unroll
        for (int ky = 0; ky < 3; ky++) {
            const float* row = &st[buf][ty + ky][tx * 8];
            float4 t0 = *(const float4*)row;
            float4 t1 = *(const float4*)(row + 4);
            float t8 = row[8], t9 = row[9];
            unsigned long long xx[10];
            xx[0]=pack2(t0.x); xx[1]=pack2(t0.y); xx[2]=pack2(t0.z); xx[3]=pack2(t0.w);
            xx[4]=pack2(t1.x); xx[5]=pack2(t1.y); xx[6]=pack2(t1.z); xx[7]=pack2(t1.w);
            xx[8]=pack2(t8);   xx[9]=pack2(t9);
            #pragma unroll
            for (int kx = 0; kx < 3; kx++) {
                const ulonglong2* wp = (const ulonglong2*)&swT[(ci * 9 + ky * 3 + kx) * 8];
                ulonglong2 wA = wp[0], wB = wp[1];
                #pragma unroll
                for (int p = 0; p < 8; p++) {
                    unsigned long long xv = xx[p + kx];
                    fma2(acc[p][0], xv, wA.x);
                    fma2(acc[p][1], xv, wA.y);
                    fma2(acc[p][2], xv, wB.x);
                    fma2(acc[p][3], xv, wB.y);
                }
            }
        }
        __syncthreads();
    }
    // epilogue: unpack [px][co-pair] -> v[px][co]
    float v[8][8];
    #pragma unroll
    for (int p = 0; p < 8; p++) {
        #pragma unroll
        for (int j = 0; j < 4; j++) {
            float2 u = unpack2(acc[p][j]);
            v[p][2*j] = u.x; v[p][2*j+1] = u.y;
        }
    }
    int yy = y0 + ty, xb = x0 + tx * 8;
    #pragma unroll
    for (int co = 0; co < 8; co++) {
        int oc = grp * 8 + co;
        float b = g_bgate[oc];
        float4 A, B;
        A.x=v[0][co]+b; A.y=v[1][co]+b; A.z=v[2][co]+b; A.w=v[3][co]+b;
        B.x=v[4][co]+b; B.y=v[5][co]+b; B.z=v[6][co]+b; B.w=v[7][co]+b;
        if (oc < 24) {
            float* dst = &g_fic[((size_t)n * 24 + oc) * HW + yy * WW + xb];
            *(float4*)dst = A; *(float4*)(dst + 4) = B;
        } else {
            A.x=sigm(A.x); A.y=sigm(A.y); A.z=sigm(A.z); A.w=sigm(A.w);
            B.x=sigm(B.x); B.y=sigm(B.y); B.z=sigm(B.z); B.w=sigm(B.w);
            float* dst = &g_r[((size_t)n * NFH + 8 + (oc - 24)) * HW + yy * WW + xb];
            *(float4*)dst = A; *(float4*)(dst + 4) = B;
        }
    }
}

// ---------------- LSTM cell state update ----------------
__global__ void cs_update() {
    int i = blockIdx.x * 256 + threadIdx.x;
    if (i >= BB * 8 * HW) return;
    int n = i / (8 * HW);
    int r = i % (8 * HW);
    int c = r / HW, p = r % HW;
    size_t base = (size_t)n * 24 * HW + p;
    float zf = g_fic[base + (size_t)c * HW];
    float zi = g_fic[base + (size_t)(8 + c) * HW];
    float zc = g_fic[base + (size_t)(16 + c) * HW];
    float cs = sigm(zf) * g_cs[i] + sigm(zi) * tanhf(zc);
    g_cs[i] = cs;
    g_r[((size_t)n * NFH + c) * HW + p] = cs;
}

// ---------------- 5x5 conv 40->40, f32x2, 64x16 tile, 8px x 8co/thread + BN partials ----
// PHASE 0: in = g_r (raw), out = g_y0.  PHASE 1: in = BN0+relu(g_y0), out = g_y1.
template <int PHASE>
__global__ __launch_bounds__(128, 3) void conv5_kernel(const float* __restrict__ Wt) {
    __shared__ float swT[NFH * 25 * 8];   // [ci][k][co] 8000 f = 32KB
    __shared__ float st[2][20][72];       // ping-pong, 68 cols used, 11.5KB
    __shared__ float red[2][4][8];
    int n = blockIdx.z / 5, cog = blockIdx.z % 5;
    int tx = threadIdx.x, ty = threadIdx.y;
    int tid = ty * 8 + tx;
    for (int i = tid; i < 8 * NFH * 25; i += 128) {
        int o = i / (NFH * 25), r = i % (NFH * 25);
        swT[r * 8 + o] = Wt[(cog * 8) * (NFH * 25) + i];
    }
    unsigned long long acc[8][4];
    #pragma unroll
    for (int p = 0; p < 8; p++) { acc[p][0]=acc[p][1]=acc[p][2]=acc[p][3]=0ull; }
    int y0 = blockIdx.y * 16, x0 = blockIdx.x * 64;

    auto loadci = [&](int ci, int buf) {
        const float* src = (PHASE ? g_y0 : g_r) + ((size_t)n * NFH + ci) * HW;
        float a = 0.f, b = 0.f;
        if (PHASE) { a = g_bna[0][ci]; b = g_bnb[0][ci]; }
        for (int i = tid; i < 20 * 68; i += 128) {
            int r = i / 68, c = i % 68;
            int yy = y0 - 2 + r, xx = x0 - 2 + c;
            float v = 0.f;
            if (yy >= 0 && yy < HH && xx >= 0 && xx < WW) {
                v = src[yy * WW + xx];
                if (PHASE) v = fmaxf(0.f, fmaf(v, a, b));
            }
            st[buf][r][c] = v;
        }
    };

    loadci(0, 0);
    __syncthreads();
    for (int ci = 0; ci < NFH; ci++) {
        if (ci + 1 < NFH) loadci(ci + 1, (ci + 1) & 1);
        int buf = ci & 1;
        #pragma unroll
        for (int ky = 0; ky < 5; ky++) {
            const float* row = &st[buf][ty + ky][tx * 8];
            float4 t0 = *(const float4*)row;
            float4 t1 = *(const float4*)(row + 4);
            float4 t2 = *(const float4*)(row + 8);
            unsigned long long xx[12];
            xx[0]=pack2(t0.x); xx[1]=pack2(t0.y); xx[2]=pack2(t0.z);  xx[3]=pack2(t0.w);
            xx[4]=pack2(t1.x); xx[5]=pack2(t1.y); xx[6]=pack2(t1.z);  xx[7]=pack2(t1.w);
            xx[8]=pack2(t2.x); xx[9]=pack2(t2.y); xx[10]=pack2(t2.z); xx[11]=pack2(t2.w);
            #pragma unroll
            for (int kx = 0; kx < 5; kx++) {
                const ulonglong2* wp = (const ulonglong2*)&swT[(ci * 25 + ky * 5 + kx) * 8];
                ulonglong2 wA = wp[0], wB = wp[1];
                #pragma unroll
                for (int p = 0; p < 8; p++) {
                    unsigned long long xv = xx[p + kx];
                    fma2(acc[p][0], xv, wA.x);
                    fma2(acc[p][1], xv, wA.y);
                    fma2(acc[p][2], xv, wB.x);
                    fma2(acc[p][3], xv, wB.y);
                }
            }
        }
        __syncthreads();
    }
    // epilogue: unpack, store raw conv out, emit BN partials
    float v[8][8];
    #pragma unroll
    for (int p = 0; p < 8; p++) {
        #pragma unroll
        for (int j = 0; j < 4; j++) {
            float2 u = unpack2(acc[p][j]);
            v[p][2*j] = u.x; v[p][2*j+1] = u.y;
        }
    }
    float* outp = PHASE ? g_y1 : g_y0;
    int yy = y0 + ty, xb = x0 + tx * 8;
    float s[8], q[8];
    #pragma unroll
    for (int co = 0; co < 8; co++) {
        float4 A, B;
        A.x=v[0][co]; A.y=v[1][co]; A.z=v[2][co]; A.w=v[3][co];
        B.x=v[4][co]; B.y=v[5][co]; B.z=v[6][co]; B.w=v[7][co];
        float* dst = &outp[((size_t)n * NFH + cog * 8 + co) * HW + yy * WW + xb];
        *(float4*)dst = A; *(float4*)(dst + 4) = B;
        s[co] = (A.x + A.y + A.z + A.w) + (B.x + B.y + B.z + B.w);
        q[co] = (A.x*A.x + A.y*A.y + A.z*A.z + A.w*A.w)
              + (B.x*B.x + B.y*B.y + B.z*B.z + B.w*B.w);
    }
    int lane = tid & 31, warp = tid >> 5;
    #pragma unroll
    for (int off = 16; off; off >>= 1) {
        #pragma unroll
        for (int co = 0; co < 8; co++) {
            s[co] += __shfl_down_sync(0xffffffffu, s[co], off);
            q[co] += __shfl_down_sync(0xffffffffu, q[co], off);
        }
    }
    if (lane == 0) {
        #pragma unroll
        for (int co = 0; co < 8; co++) { red[0][warp][co] = s[co]; red[1][warp][co] = q[co]; }
    }
    __syncthreads();
    if (tid < 8) {
        float S = red[0][0][tid] + red[0][1][tid] + red[0][2][tid] + red[0][3][tid];
        float Q = red[1][0][tid] + red[1][1][tid] + red[1][2][tid] + red[1][3][tid];
        int ch = cog * 8 + tid;
        int bxy = (n * 12 + blockIdx.y) * 3 + blockIdx.x;
        g_partS[ch * NPART + bxy] = S;
        g_partQ[ch * NPART + bxy] = Q;
    }
}

// ---------------- BN statistics finalize ----------------
__global__ void bn_reduce(int phase, const float* __restrict__ gamma, const float* __restrict__ beta) {
    int ch = blockIdx.x;
    int tid = threadIdx.x;
    __shared__ float ss[128], sq[128];
    float s = 0.f, q = 0.f;
    for (int i = tid; i < NPART; i += 128) { s += g_partS[ch * NPART + i]; q += g_partQ[ch * NPART + i]; }
    ss[tid] = s; sq[tid] = q;
    __syncthreads();
    for (int off = 64; off; off >>= 1) {
        if (tid < off) { ss[tid] += ss[tid + off]; sq[tid] += sq[tid + off]; }
        __syncthreads();
    }
    if (tid == 0) {
        const float N = (float)(BB * HW);
        float mean = ss[0] / N;
        float var = sq[0] / N - mean * mean;
        float inv = rsqrtf(var + EPS);
        float a = gamma[ch] * inv;
        g_bna[phase][ch] = a;
        g_bnb[phase][ch] = beta[ch] - mean * a;
    }
}

// ---------------- tail: combined 5x5 conv, 40 -> 12(pad), f32x2, 32x16 tile ------------
// weights streamed from global (uniform LDG, L1-broadcast), layout [ci*25+tap][12co]
__global__ __launch_bounds__(128, 4) void tail_kernel(float* __restrict__ outp, int t) {
    __shared__ float st[2][20][40];   // 36 cols used
    int n = blockIdx.z;
    int tx = threadIdx.x, ty = threadIdx.y;
    int tid = ty * 8 + tx;
    unsigned long long acc[4][6];
    #pragma unroll
    for (int p = 0; p < 4; p++)
        #pragma unroll
        for (int j = 0; j < 6; j++) acc[p][j] = 0ull;
    int y0 = blockIdx.y * 16, x0 = blockIdx.x * 32;

    auto loadci = [&](int ci, int buf) {
        const float* src = g_y1 + ((size_t)n * NFH + ci) * HW;
        float a = g_bna[1][ci], b = g_bnb[1][ci];
        for (int i = tid; i < 20 * 36; i += 128) {
            int r = i / 36, c = i % 36;
            int yy = y0 - 2 + r, xx = x0 - 2 + c;
            float v = 0.f;
            if (yy >= 0 && yy < HH && xx >= 0 && xx < WW)
                v = fmaxf(0.f, fmaf(src[yy * WW + xx], a, b));
            st[buf][r][c] = v;
        }
    };

    loadci(0, 0);
    __syncthreads();
    for (int ci = 0; ci < NFH; ci++) {
        if (ci + 1 < NFH) loadci(ci + 1, (ci + 1) & 1);
        int buf = ci & 1;
        #pragma unroll
        for (int ky = 0; ky < 5; ky++) {
            const float* row = &st[buf][ty + ky][tx * 4];
            float4 t0 = *(const float4*)row;
            float4 t1 = *(const float4*)(row + 4);
            unsigned long long xx[8];
            xx[0]=pack2(t0.x); xx[1]=pack2(t0.y); xx[2]=pack2(t0.z); xx[3]=pack2(t0.w);
            xx[4]=pack2(t1.x); xx[5]=pack2(t1.y); xx[6]=pack2(t1.z); xx[7]=pack2(t1.w);
            #pragma unroll
            for (int kx = 0; kx < 5; kx++) {
                const ulonglong2* wp =
                    (const ulonglong2*)&g_wtailT[(ci * 25 + ky * 5 + kx) * 12];
                ulonglong2 wA = __ldg(wp), wB = __ldg(wp + 1), wC = __ldg(wp + 2);
                #pragma unroll
                for (int p = 0; p < 4; p++) {
                    unsigned long long xv = xx[p + kx];
                    fma2(acc[p][0], xv, wA.x);
                    fma2(acc[p][1], xv, wA.y);
                    fma2(acc[p][2], xv, wB.x);
                    fma2(acc[p][3], xv, wB.y);
                    fma2(acc[p][4], xv, wC.x);
                    fma2(acc[p][5], xv, wC.y);
                }
            }
        }
        __syncthreads();
    }
    // epilogue: co = 2j+(0,1), co<3 -> depth out, co 3..10 -> h state, co11 pad dropped
    float v[4][12];
    #pragma unroll
    for (int p = 0; p < 4; p++) {
        #pragma unroll
        for (int j = 0; j < 6; j++) {
            float2 u = unpack2(acc[p][j]);
            v[p][2*j] = u.x; v[p][2*j+1] = u.y;
        }
    }
    int yy = y0 + ty, xb = x0 + tx * 4;
    #pragma unroll
    for (int co = 0; co < 11; co++) {
        float b = g_btail[co];
        float4 o; o.x=v[0][co]+b; o.y=v[1][co]+b; o.z=v[2][co]+b; o.w=v[3][co]+b;
        if (co < 3) {
            *(float4*)&outp[(((size_t)n * 3 + co) * DD + t) * HW + yy * WW + xb] = o;
        } else {
            *(float4*)&g_hs[((size_t)n * 8 + (co - 3)) * HW + yy * WW + xb] = o;
        }
    }
}

// ---------------- launcher ----------------
extern "C" void kernel_launch(void* const* d_in, const int* in_sizes, int n_in,
                              void* d_out, int out_size) {
    const float* x1  = (const float*)d_in[0];
    const float* x2  = (const float*)d_in[1];
    const float* Wf  = (const float*)d_in[2];
    const float* bf  = (const float*)d_in[3];
    const float* Wi  = (const float*)d_in[4];
    const float* bi  = (const float*)d_in[5];
    const float* Wc  = (const float*)d_in[6];
    const float* bc  = (const float*)d_in[7];
    const float* Wq  = (const float*)d_in[8];
    const float* bq  = (const float*)d_in[9];
    const float* W0  = (const float*)d_in[10];
    const float* g0  = (const float*)d_in[11];
    const float* be0 = (const float*)d_in[12];
    const float* W1  = (const float*)d_in[13];
    const float* g1  = (const float*)d_in[14];
    const float* be1 = (const float*)d_in[15];
    const float* W2  = (const float*)d_in[16];
    const float* b2w = (const float*)d_in[17];
    const float* Wh  = (const float*)d_in[18];
    const float* bh  = (const float*)d_in[19];
    float* out = (float*)d_out;

    dim3 cb(8, 16, 1);
    dim3 gGate(3, 12, BB * 7);
    dim3 gConv(3, 12, BB * 5);
    dim3 gTail(6, 12, BB);

    zero_state<<<(BB*8*HW + 255) / 256, 256>>>();
    prep_gate<<<(CGATE*NFH*9 + 255) / 256, 256>>>(Wf, bf, Wi, bi, Wc, bc, Wq, bq);
    prep_tail<<<(NFH*25*12 + 255) / 256, 256>>>(W2, b2w, Wh, bh);

    const size_t OUT_HALF = (size_t)BB * 3 * DD * HW;
    for (int t = 0; t < DD; t++) {
        for (int cell = 0; cell < 2; cell++) {
            gates_kernel<<<gGate, cb>>>(cell ? x2 : x1, t);
            cs_update<<<(BB*8*HW + 255) / 256, 256>>>();
            conv5_kernel<0><<<gConv, cb>>>(W0);
            bn_reduce<<<NFH, 128>>>(0, g0, be0);
            conv5_kernel<1><<<gConv, cb>>>(W1);
            bn_reduce<<<NFH, 128>>>(1, g1, be1);
            tail_kernel<<<gTail, cb>>>(out + (size_t)cell * OUT_HALF, t);
        }
    }
}